// round 16
// baseline (speedup 1.0000x reference)
#include <cuda_runtime.h>
#include <cstddef>

// Shapes (fixed per reference): B=16, Cin=Cout=256, S=512, H=W=64, K=3
#define BATCH 16
#define CINC  256
#define COUTC 256
#define SDIM  512
#define HH    64
#define WW    64

// Conv tiling
#define CK     8      // cin per chunk
#define COUT_T 32     // couts per block
#define H_T    4      // output rows per block
#define XH     6      // H_T + 2 (halo)
#define XW     66     // WW + 2 (halo); row stride 264B = 8B-aligned

// Scratch (static device globals — no allocation allowed)
__device__ float g_style[BATCH * CINC];   // style[b][cin]
__device__ float g_wsq[COUTC * CINC];     // sum_kk w^2 per (cout,cin)
__device__ float g_demod[BATCH * COUTC];  // 1/sqrt(sum + eps)

// Packed dual-fp32 FMA (Blackwell): d = a*b + c, two lanes per instruction.
__device__ __forceinline__ float2 ffma2(float2 a, float2 b, float2 c) {
    float2 d;
    asm("fma.rn.f32x2 %0, %1, %2, %3;"
        : "=l"(*reinterpret_cast<unsigned long long*>(&d))
        : "l"(*reinterpret_cast<unsigned long long*>(&a)),
          "l"(*reinterpret_cast<unsigned long long*>(&b)),
          "l"(*reinterpret_cast<unsigned long long*>(&c)));
    return d;
}

// ---------------------------------------------------------------------------
// Kernel 1: style[b][c] = y[b] . style_w[c] + style_b[c]   (one warp per (b,c))
// ---------------------------------------------------------------------------
__global__ void style_kernel(const float* __restrict__ y,
                             const float* __restrict__ sw,
                             const float* __restrict__ sb) {
    int gwarp = (blockIdx.x * blockDim.x + threadIdx.x) >> 5;
    int lane  = threadIdx.x & 31;
    if (gwarp >= BATCH * CINC) return;
    int b = gwarp >> 8;
    int c = gwarp & 255;
    const float* yr = y + (size_t)b * SDIM;
    const float* wr = sw + (size_t)c * SDIM;
    float s = 0.f;
    #pragma unroll 4
    for (int i = lane; i < SDIM; i += 32) s += yr[i] * wr[i];
    #pragma unroll
    for (int o = 16; o; o >>= 1) s += __shfl_xor_sync(0xffffffffu, s, o);
    if (lane == 0) g_style[gwarp] = s + sb[c];
}

// ---------------------------------------------------------------------------
// Kernel 2: wsq[co][ci] = sum_kk w[co][ci][kk]^2
// ---------------------------------------------------------------------------
__global__ void wsq_kernel(const float* __restrict__ w) {
    int i = blockIdx.x * blockDim.x + threadIdx.x;
    if (i >= COUTC * CINC) return;
    const float* p = w + (size_t)i * 9;
    float s = 0.f;
    #pragma unroll
    for (int k = 0; k < 9; ++k) s += p[k] * p[k];
    g_wsq[i] = s;
}

// ---------------------------------------------------------------------------
// Kernel 3: demod[b][co] = rsqrt( sum_ci style[b][ci]^2 * wsq[co][ci] + eps )
// ---------------------------------------------------------------------------
__global__ void demod_kernel() {
    int gwarp = (blockIdx.x * blockDim.x + threadIdx.x) >> 5;
    int lane  = threadIdx.x & 31;
    if (gwarp >= BATCH * COUTC) return;
    int b  = gwarp >> 8;
    int co = gwarp & 255;
    float s = 0.f;
    #pragma unroll 2
    for (int c = lane; c < CINC; c += 32) {
        float st = g_style[b * CINC + c];
        s += st * st * g_wsq[co * CINC + c];
    }
    #pragma unroll
    for (int o = 16; o; o >>= 1) s += __shfl_xor_sync(0xffffffffu, s, o);
    if (lane == 0) g_demod[gwarp] = rsqrtf(s + 1e-8f);
}

// ---------------------------------------------------------------------------
// Kernel 4: conv with packed f32x2 FMA.
//   Block = 256 threads (8 warps). Tile: 32 couts x 4 rows x 64 cols.
//   Warp owns 4 couts; thread owns output col pair (2*lane, 2*lane+1) x 4 rows
//   x 4 couts = 16 float2 accumulators.
//   Per cin: 6 row-pairs loaded once via aligned LDS.64; kx=1 operand is a
//   single pack {P0.y,P1.x}. Weights staged duplicated as float2{w,w} so the
//   broadcast operand is one LDS.64.
// ---------------------------------------------------------------------------
__global__ __launch_bounds__(256, 2)
void conv_kernel(const float* __restrict__ x,
                 const float* __restrict__ wgt,
                 const float* __restrict__ bias,
                 float* __restrict__ out) {
    __shared__ __align__(16) float  sx[CK][XH][XW];          // 12672 B
    __shared__ __align__(16) float2 swt2[COUT_T][CK][9];     // 18432 B
    __shared__ float ssty[CINC];                             // 1024 B

    const int tid  = threadIdx.x;
    const int lane = tid & 31;
    const int warp = tid >> 5;
    const int h0   = blockIdx.x * H_T;
    const int co0  = blockIdx.y * COUT_T;
    const int b    = blockIdx.z;
    const int col2 = lane * 2;   // base column in sx coords (global col - 1 + 1)

    // preload all styles for this batch sample
    ssty[tid] = g_style[b * CINC + tid];
    __syncthreads();

    float2 acc[4][4];
    #pragma unroll
    for (int a = 0; a < 4; ++a)
        #pragma unroll
        for (int h = 0; h < 4; ++h) acc[a][h] = make_float2(0.f, 0.f);

    const size_t x_b = (size_t)b * CINC * HH * WW;
    float2* swt_flat = &swt2[0][0][0];

    for (int ci0 = 0; ci0 < CINC; ci0 += CK) {
        // ---- stage x tile (style-scaled, zero halo) ----
        #pragma unroll
        for (int i = tid; i < CK * XH * XW; i += 256) {
            int cin = i / (XH * XW);
            int rem = i - cin * (XH * XW);
            int r   = rem / XW;
            int c   = rem - r * XW;
            int gh  = h0 + r - 1;
            int gw  = c - 1;
            float v = 0.f;
            if ((unsigned)gh < (unsigned)HH && (unsigned)gw < (unsigned)WW)
                v = x[x_b + ((size_t)(ci0 + cin) * HH + gh) * WW + gw] * ssty[ci0 + cin];
            sx[cin][r][c] = v;
        }
        // ---- stage weight tile, duplicated to float2 ----
        #pragma unroll
        for (int i = tid; i < COUT_T * CK * 9; i += 256) {
            int co  = i / (CK * 9);
            int rem = i - co * (CK * 9);
            int cin = rem / 9;
            int kk  = rem - cin * 9;
            float w = wgt[((size_t)(co0 + co) * CINC + ci0 + cin) * 9 + kk];
            swt_flat[i] = make_float2(w, w);
        }
        __syncthreads();

        // ---- compute ----
        #pragma unroll
        for (int cin = 0; cin < CK; ++cin) {
            // 6 rows of input pairs, loaded once, reused across ky
            float2 P0[XH], P1[XH], M[XH];
            #pragma unroll
            for (int r = 0; r < XH; ++r) {
                P0[r] = *reinterpret_cast<const float2*>(&sx[cin][r][col2]);
                P1[r] = *reinterpret_cast<const float2*>(&sx[cin][r][col2 + 2]);
                M[r]  = make_float2(P0[r].y, P1[r].x);
            }
            #pragma unroll
            for (int ky = 0; ky < 3; ++ky) {
                #pragma unroll
                for (int kx = 0; kx < 3; ++kx) {
                    float2 wv[4];
                    #pragma unroll
                    for (int co = 0; co < 4; ++co)
                        wv[co] = swt2[warp * 4 + co][cin][ky * 3 + kx];
                    #pragma unroll
                    for (int co = 0; co < 4; ++co) {
                        #pragma unroll
                        for (int h = 0; h < 4; ++h) {
                            float2 v = (kx == 0) ? P0[h + ky]
                                     : (kx == 1) ? M[h + ky]
                                                 : P1[h + ky];
                            acc[co][h] = ffma2(v, wv[co], acc[co][h]);
                        }
                    }
                }
            }
        }
        __syncthreads();
    }

    // ---- epilogue: demod scale + bias, STG.64 ----
    #pragma unroll
    for (int a = 0; a < 4; ++a) {
        int cog  = co0 + warp * 4 + a;
        float dm = g_demod[b * COUTC + cog];
        float bv = bias[cog];
        #pragma unroll
        for (int h = 0; h < 4; ++h) {
            size_t base = (((size_t)b * COUTC + cog) * HH + h0 + h) * WW;
            float2 r = acc[a][h];
            r.x = r.x * dm + bv;
            r.y = r.y * dm + bv;
            *reinterpret_cast<float2*>(&out[base + col2]) = r;
        }
    }
}

// ---------------------------------------------------------------------------
// Launch. Inputs in metadata order:
//   d_in[0]=x [16,256,64,64], d_in[1]=y [16,512], d_in[2]=weights [256,256,3,3],
//   d_in[3]=bias [256], d_in[4]=style_w [256,512], d_in[5]=style_b [256]
// out: [16,256,64,64] f32
// ---------------------------------------------------------------------------
extern "C" void kernel_launch(void* const* d_in, const int* in_sizes, int n_in,
                              void* d_out, int out_size) {
    const float* x       = (const float*)d_in[0];
    const float* y       = (const float*)d_in[1];
    const float* weights = (const float*)d_in[2];
    const float* bias    = (const float*)d_in[3];
    const float* style_w = (const float*)d_in[4];
    const float* style_b = (const float*)d_in[5];
    float* out = (float*)d_out;

    style_kernel<<<512, 256>>>(y, style_w, style_b);
    wsq_kernel<<<(COUTC * CINC + 255) / 256, 256>>>(weights);
    demod_kernel<<<512, 256>>>();
    dim3 grid(HH / H_T, COUTC / COUT_T, BATCH);
    conv_kernel<<<grid, 256>>>(x, weights, bias, out);
}